// round 12
// baseline (speedup 1.0000x reference)
#include <cuda_runtime.h>
#include <mma.h>
#include <math.h>

using namespace nvcuda;

#define T_TOK 524288
#define D_DIM 256
#define N_SEG 8192

__device__ __align__(16) float g_mean[N_SEG * D_DIM];
__device__ __align__(16) float g_tg[N_SEG * D_DIM];
__device__ int g_segstart[N_SEG + 1];

// ---------------------------------------------------------------------------
// Pass 0: segment boundaries from sorted obj.
// ---------------------------------------------------------------------------
__global__ void k_bounds(const int* __restrict__ obj) {
    int t = blockIdx.x * blockDim.x + threadIdx.x;
    if (t >= T_TOK) return;
    if (t == 0) {
        int v0 = obj[0];
        for (int j = 0; j <= v0; ++j) g_segstart[j] = 0;
        int vl = obj[T_TOK - 1];
        for (int j = vl + 1; j <= N_SEG; ++j) g_segstart[j] = T_TOK;
    } else {
        int p = obj[t - 1], c = obj[t];
        for (int j = p + 1; j <= c; ++j) g_segstart[j] = t;
    }
}

// ---------------------------------------------------------------------------
// Pass 1: per-segment mean. One 512-thread block per segment.
// ---------------------------------------------------------------------------
__global__ void __launch_bounds__(512)
k_segmean(const float* __restrict__ emb) {
    int n = blockIdx.x, tid = threadIdx.x;
    __shared__ __align__(16) float red[8][256];
    int s = g_segstart[n], e = g_segstart[n + 1];

    int r = tid >> 6;
    int c4 = (tid & 63) * 4;
    const float4* base = (const float4*)emb + (c4 >> 2);

    float4 acc = make_float4(0.f, 0.f, 0.f, 0.f);
#pragma unroll 4
    for (int t = s + r; t < e; t += 8) {
        float4 v = __ldcs(base + (size_t)t * 64);
        acc.x += v.x; acc.y += v.y; acc.z += v.z; acc.w += v.w;
    }
    *(float4*)&red[r][c4] = acc;
    __syncthreads();

    if (tid < 256) {
        float sum = 0.f;
#pragma unroll
        for (int j = 0; j < 8; ++j) sum += red[j][tid];
        g_mean[(size_t)n * D_DIM + tid] = sum / fmaxf((float)(e - s), 1.f);
    }
}

// ---------------------------------------------------------------------------
// Pass 2: g_tg = tanh(g_mean @ W) via 3xTF32 wmma. hi/lo split done ONCE at
// smem staging: inner loop is pure load_matrix_sync + mma_sync.
// Block 256 thr = 8 warps; block tile 128x64; warp tile 32x32 (2x2 frags).
// ---------------------------------------------------------------------------
#define AS_LD 36
#define BS_LD 68

__global__ void __launch_bounds__(256)
k_gemm_tanh(const float* __restrict__ W) {
    __shared__ __align__(16) float Ah[128][AS_LD], Al[128][AS_LD];
    __shared__ __align__(16) float Bh[32][BS_LD],  Bl[32][BS_LD];
    int tid = threadIdx.x;
    int w = tid >> 5;
    int wm = w >> 1, wn = w & 1;          // 4 warps in M, 2 in N
    int bm = blockIdx.x * 128, bn = blockIdx.y * 64;

    wmma::fragment<wmma::accumulator, 16, 16, 8, float> acc[2][2];
#pragma unroll
    for (int i = 0; i < 2; ++i)
#pragma unroll
        for (int j = 0; j < 2; ++j)
            wmma::fill_fragment(acc[i][j], 0.f);

    for (int k0 = 0; k0 < 256; k0 += 32) {
        // Stage A slab with hi/lo split: 128 x 32 (1024 float4, 4/thread)
#pragma unroll
        for (int q = 0; q < 4; ++q) {
            int f = tid + q * 256;
            int row = f >> 3, c4 = (f & 7) * 4;
            float4 v = *(const float4*)(g_mean + (size_t)(bm + row) * 256 + k0 + c4);
            float hx = wmma::__float_to_tf32(v.x);
            float hy = wmma::__float_to_tf32(v.y);
            float hz = wmma::__float_to_tf32(v.z);
            float hw = wmma::__float_to_tf32(v.w);
            Ah[row][c4+0] = hx; Al[row][c4+0] = wmma::__float_to_tf32(v.x - hx);
            Ah[row][c4+1] = hy; Al[row][c4+1] = wmma::__float_to_tf32(v.y - hy);
            Ah[row][c4+2] = hz; Al[row][c4+2] = wmma::__float_to_tf32(v.z - hz);
            Ah[row][c4+3] = hw; Al[row][c4+3] = wmma::__float_to_tf32(v.w - hw);
        }
        // Stage B slab with hi/lo split: 32 x 64 (512 float4, 2/thread)
#pragma unroll
        for (int q = 0; q < 2; ++q) {
            int f = tid + q * 256;
            int row = f >> 4, c4 = (f & 15) * 4;
            float4 v = *(const float4*)(W + (size_t)(k0 + row) * 256 + bn + c4);
            float hx = wmma::__float_to_tf32(v.x);
            float hy = wmma::__float_to_tf32(v.y);
            float hz = wmma::__float_to_tf32(v.z);
            float hw = wmma::__float_to_tf32(v.w);
            Bh[row][c4+0] = hx; Bl[row][c4+0] = wmma::__float_to_tf32(v.x - hx);
            Bh[row][c4+1] = hy; Bl[row][c4+1] = wmma::__float_to_tf32(v.y - hy);
            Bh[row][c4+2] = hz; Bl[row][c4+2] = wmma::__float_to_tf32(v.z - hz);
            Bh[row][c4+3] = hw; Bl[row][c4+3] = wmma::__float_to_tf32(v.w - hw);
        }
        __syncthreads();

#pragma unroll
        for (int ks = 0; ks < 4; ++ks) {
            wmma::fragment<wmma::matrix_a, 16, 16, 8, wmma::precision::tf32, wmma::row_major> ahi[2], alo[2];
            wmma::fragment<wmma::matrix_b, 16, 16, 8, wmma::precision::tf32, wmma::row_major> bhi[2], blo[2];
#pragma unroll
            for (int i = 0; i < 2; ++i) {
                wmma::load_matrix_sync(ahi[i], &Ah[wm * 32 + i * 16][ks * 8], AS_LD);
                wmma::load_matrix_sync(alo[i], &Al[wm * 32 + i * 16][ks * 8], AS_LD);
            }
#pragma unroll
            for (int j = 0; j < 2; ++j) {
                wmma::load_matrix_sync(bhi[j], &Bh[ks * 8][wn * 32 + j * 16], BS_LD);
                wmma::load_matrix_sync(blo[j], &Bl[ks * 8][wn * 32 + j * 16], BS_LD);
            }
#pragma unroll
            for (int i = 0; i < 2; ++i)
#pragma unroll
                for (int j = 0; j < 2; ++j) {
                    wmma::mma_sync(acc[i][j], ahi[i], blo[j], acc[i][j]);
                    wmma::mma_sync(acc[i][j], alo[i], bhi[j], acc[i][j]);
                    wmma::mma_sync(acc[i][j], ahi[i], bhi[j], acc[i][j]);
                }
        }
        __syncthreads();
    }

#pragma unroll
    for (int i = 0; i < 2; ++i)
#pragma unroll
        for (int j = 0; j < 2; ++j) {
#pragma unroll
            for (int x = 0; x < acc[i][j].num_elements; ++x)
                acc[i][j].x[x] = tanhf(acc[i][j].x[x]);
            int row = bm + wm * 32 + i * 16;
            int col = bn + wn * 32 + j * 16;
            wmma::store_matrix_sync(g_tg + (size_t)row * 256 + col, acc[i][j],
                                    256, wmma::mem_row_major);
        }
}

// ---------------------------------------------------------------------------
// Pass 3 (fused): scores + weighted segment sum + broadcast.
// ---------------------------------------------------------------------------
__global__ void __launch_bounds__(256, 6)
k_score_rep_bcast(const float* __restrict__ emb, float* __restrict__ out) {
    int n = blockIdx.x, tid = threadIdx.x;
    __shared__ __align__(16) float stg[256];
    __shared__ __align__(16) float redw[8][256];
    __shared__ __align__(16) float srep[256];
    int s = g_segstart[n], e = g_segstart[n + 1];
    stg[tid] = g_tg[(size_t)n * 256 + tid];
    __syncthreads();
    int lane = tid & 31, w = tid >> 5;

    float4 tga = *(const float4*)&stg[lane * 8];
    float4 tgb = *(const float4*)&stg[lane * 8 + 4];
    float4 accA = make_float4(0.f, 0.f, 0.f, 0.f);
    float4 accB = make_float4(0.f, 0.f, 0.f, 0.f);

    const float4* base = (const float4*)emb + lane * 2;

    int t = s + 2 * w;
    for (; t + 1 < e; t += 16) {
        float4 a0 = __ldcs(base + (size_t)(t + 0) * 64);
        float4 b0 = __ldcs(base + (size_t)(t + 0) * 64 + 1);
        float4 a1 = __ldcs(base + (size_t)(t + 1) * 64);
        float4 b1 = __ldcs(base + (size_t)(t + 1) * 64 + 1);
        float d0 = a0.x*tga.x + a0.y*tga.y + a0.z*tga.z + a0.w*tga.w
                 + b0.x*tgb.x + b0.y*tgb.y + b0.z*tgb.z + b0.w*tgb.w;
        float d1 = a1.x*tga.x + a1.y*tga.y + a1.z*tga.z + a1.w*tga.w
                 + b1.x*tgb.x + b1.y*tgb.y + b1.z*tgb.z + b1.w*tgb.w;
#pragma unroll
        for (int off = 16; off; off >>= 1) {
            d0 += __shfl_xor_sync(0xffffffffu, d0, off);
            d1 += __shfl_xor_sync(0xffffffffu, d1, off);
        }
        float s0 = 1.f / (1.f + __expf(-d0));
        float s1 = 1.f / (1.f + __expf(-d1));
        accA.x += a0.x*s0 + a1.x*s1;
        accA.y += a0.y*s0 + a1.y*s1;
        accA.z += a0.z*s0 + a1.z*s1;
        accA.w += a0.w*s0 + a1.w*s1;
        accB.x += b0.x*s0 + b1.x*s1;
        accB.y += b0.y*s0 + b1.y*s1;
        accB.z += b0.z*s0 + b1.z*s1;
        accB.w += b0.w*s0 + b1.w*s1;
    }
    if (t < e) {
        float4 a0 = __ldcs(base + (size_t)t * 64);
        float4 b0 = __ldcs(base + (size_t)t * 64 + 1);
        float d0 = a0.x*tga.x + a0.y*tga.y + a0.z*tga.z + a0.w*tga.w
                 + b0.x*tgb.x + b0.y*tgb.y + b0.z*tgb.z + b0.w*tgb.w;
#pragma unroll
        for (int off = 16; off; off >>= 1)
            d0 += __shfl_xor_sync(0xffffffffu, d0, off);
        float s0 = 1.f / (1.f + __expf(-d0));
        accA.x += a0.x*s0; accA.y += a0.y*s0;
        accA.z += a0.z*s0; accA.w += a0.w*s0;
        accB.x += b0.x*s0; accB.y += b0.y*s0;
        accB.z += b0.z*s0; accB.w += b0.w*s0;
    }
    *(float4*)&redw[w][lane * 8]     = accA;
    *(float4*)&redw[w][lane * 8 + 4] = accB;
    __syncthreads();
    float sum = 0.f;
#pragma unroll
    for (int j = 0; j < 8; ++j) sum += redw[j][tid];
    srep[tid] = sum;
    __syncthreads();

    int c = tid & 63;
    int r = tid >> 6;
    float4 rv = *(const float4*)&srep[c * 4];
    float4* ob = (float4*)out + c;
    for (int tt = s + r; tt < e; tt += 4)
        __stcs(ob + (size_t)tt * 64, rv);
}

extern "C" void kernel_launch(void* const* d_in, const int* in_sizes, int n_in,
                              void* d_out, int out_size) {
    const float* emb = (const float*)d_in[0];
    const float* W   = (const float*)d_in[1];
    const int*   obj = (const int*)d_in[2];
    float*       out = (float*)d_out;

    k_bounds<<<(T_TOK + 255) / 256, 256>>>(obj);
    k_segmean<<<N_SEG, 512>>>(emb);
    k_gemm_tanh<<<dim3(N_SEG / 128, D_DIM / 64), 256>>>(W);
    k_score_rep_bcast<<<N_SEG, 256>>>(emb, out);
}

// round 13
// speedup vs baseline: 1.1028x; 1.1028x over previous
#include <cuda_runtime.h>
#include <cuda_bf16.h>
#include <mma.h>
#include <math.h>

using namespace nvcuda;

#define T_TOK 524288
#define D_DIM 256
#define N_SEG 8192

__device__ __align__(16) float g_mean[N_SEG * D_DIM];
__device__ __align__(16) float g_tg[N_SEG * D_DIM];
__device__ int g_segstart[N_SEG + 1];

// ---------------------------------------------------------------------------
// Pass 0: segment boundaries from sorted obj.
// ---------------------------------------------------------------------------
__global__ void k_bounds(const int* __restrict__ obj) {
    int t = blockIdx.x * blockDim.x + threadIdx.x;
    if (t >= T_TOK) return;
    if (t == 0) {
        int v0 = obj[0];
        for (int j = 0; j <= v0; ++j) g_segstart[j] = 0;
        int vl = obj[T_TOK - 1];
        for (int j = vl + 1; j <= N_SEG; ++j) g_segstart[j] = T_TOK;
    } else {
        int p = obj[t - 1], c = obj[t];
        for (int j = p + 1; j <= c; ++j) g_segstart[j] = t;
    }
}

// ---------------------------------------------------------------------------
// Pass 1: per-segment mean. One 512-thread block per segment.
// ---------------------------------------------------------------------------
__global__ void __launch_bounds__(512)
k_segmean(const float* __restrict__ emb) {
    int n = blockIdx.x, tid = threadIdx.x;
    __shared__ __align__(16) float red[8][256];
    int s = g_segstart[n], e = g_segstart[n + 1];

    int r = tid >> 6;
    int c4 = (tid & 63) * 4;
    const float4* base = (const float4*)emb + (c4 >> 2);

    float4 acc = make_float4(0.f, 0.f, 0.f, 0.f);
#pragma unroll 4
    for (int t = s + r; t < e; t += 8) {
        float4 v = __ldcs(base + (size_t)t * 64);
        acc.x += v.x; acc.y += v.y; acc.z += v.z; acc.w += v.w;
    }
    *(float4*)&red[r][c4] = acc;
    __syncthreads();

    if (tid < 256) {
        float sum = 0.f;
#pragma unroll
        for (int j = 0; j < 8; ++j) sum += red[j][tid];
        g_mean[(size_t)n * D_DIM + tid] = sum / fmaxf((float)(e - s), 1.f);
    }
}

// ---------------------------------------------------------------------------
// Pass 2: g_tg = tanh(g_mean @ W) via bf16 wmma (m16n16k16), 2-term split,
// 3 products: hi*hi + hi*lo + lo*hi. bf16 fragments load via LDSM (fast).
// Block 128x64, 8 warps (4 in M, 2 in N), warp tile 32x32 (2x2 frags).
// ---------------------------------------------------------------------------
#define A_LD 48   // bf16 elements per A row (mult of 16)
#define B_LD 80   // bf16 elements per B row

__global__ void __launch_bounds__(256)
k_gemm_tanh(const float* __restrict__ W) {
    __shared__ __align__(16) __nv_bfloat16 Ah[128][A_LD], Al[128][A_LD];
    __shared__ __align__(16) __nv_bfloat16 Bh[32][B_LD],  Bl[32][B_LD];
    int tid = threadIdx.x;
    int w = tid >> 5;
    int wm = w >> 1, wn = w & 1;
    int bm = blockIdx.x * 128, bn = blockIdx.y * 64;

    wmma::fragment<wmma::accumulator, 16, 16, 16, float> acc[2][2];
#pragma unroll
    for (int i = 0; i < 2; ++i)
#pragma unroll
        for (int j = 0; j < 2; ++j)
            wmma::fill_fragment(acc[i][j], 0.f);

    for (int k0 = 0; k0 < 256; k0 += 32) {
        // Stage A slab 128x32 with hi/lo split (1024 float4, 4/thread)
#pragma unroll
        for (int q = 0; q < 4; ++q) {
            int f = tid + q * 256;
            int row = f >> 3, c4 = (f & 7) * 4;
            float4 v = *(const float4*)(g_mean + (size_t)(bm + row) * 256 + k0 + c4);
            __nv_bfloat16 hx = __float2bfloat16(v.x);
            __nv_bfloat16 hy = __float2bfloat16(v.y);
            __nv_bfloat16 hz = __float2bfloat16(v.z);
            __nv_bfloat16 hw = __float2bfloat16(v.w);
            Ah[row][c4+0] = hx; Al[row][c4+0] = __float2bfloat16(v.x - __bfloat162float(hx));
            Ah[row][c4+1] = hy; Al[row][c4+1] = __float2bfloat16(v.y - __bfloat162float(hy));
            Ah[row][c4+2] = hz; Al[row][c4+2] = __float2bfloat16(v.z - __bfloat162float(hz));
            Ah[row][c4+3] = hw; Al[row][c4+3] = __float2bfloat16(v.w - __bfloat162float(hw));
        }
        // Stage B slab 32x64 with hi/lo split (512 float4, 2/thread)
#pragma unroll
        for (int q = 0; q < 2; ++q) {
            int f = tid + q * 256;
            int row = f >> 4, c4 = (f & 15) * 4;
            float4 v = *(const float4*)(W + (size_t)(k0 + row) * 256 + bn + c4);
            __nv_bfloat16 hx = __float2bfloat16(v.x);
            __nv_bfloat16 hy = __float2bfloat16(v.y);
            __nv_bfloat16 hz = __float2bfloat16(v.z);
            __nv_bfloat16 hw = __float2bfloat16(v.w);
            Bh[row][c4+0] = hx; Bl[row][c4+0] = __float2bfloat16(v.x - __bfloat162float(hx));
            Bh[row][c4+1] = hy; Bl[row][c4+1] = __float2bfloat16(v.y - __bfloat162float(hy));
            Bh[row][c4+2] = hz; Bl[row][c4+2] = __float2bfloat16(v.z - __bfloat162float(hz));
            Bh[row][c4+3] = hw; Bl[row][c4+3] = __float2bfloat16(v.w - __bfloat162float(hw));
        }
        __syncthreads();

#pragma unroll
        for (int ks = 0; ks < 2; ++ks) {
            wmma::fragment<wmma::matrix_a, 16, 16, 16, __nv_bfloat16, wmma::row_major> ahi[2], alo[2];
            wmma::fragment<wmma::matrix_b, 16, 16, 16, __nv_bfloat16, wmma::row_major> bhi[2], blo[2];
#pragma unroll
            for (int i = 0; i < 2; ++i) {
                wmma::load_matrix_sync(ahi[i], &Ah[wm * 32 + i * 16][ks * 16], A_LD);
                wmma::load_matrix_sync(alo[i], &Al[wm * 32 + i * 16][ks * 16], A_LD);
            }
#pragma unroll
            for (int j = 0; j < 2; ++j) {
                wmma::load_matrix_sync(bhi[j], &Bh[ks * 16][wn * 32 + j * 16], B_LD);
                wmma::load_matrix_sync(blo[j], &Bl[ks * 16][wn * 32 + j * 16], B_LD);
            }
#pragma unroll
            for (int i = 0; i < 2; ++i)
#pragma unroll
                for (int j = 0; j < 2; ++j) {
                    wmma::mma_sync(acc[i][j], ahi[i], blo[j], acc[i][j]);
                    wmma::mma_sync(acc[i][j], alo[i], bhi[j], acc[i][j]);
                    wmma::mma_sync(acc[i][j], ahi[i], bhi[j], acc[i][j]);
                }
        }
        __syncthreads();
    }

#pragma unroll
    for (int i = 0; i < 2; ++i)
#pragma unroll
        for (int j = 0; j < 2; ++j) {
#pragma unroll
            for (int x = 0; x < acc[i][j].num_elements; ++x)
                acc[i][j].x[x] = tanhf(acc[i][j].x[x]);
            int row = bm + wm * 32 + i * 16;
            int col = bn + wn * 32 + j * 16;
            wmma::store_matrix_sync(g_tg + (size_t)row * 256 + col, acc[i][j],
                                    256, wmma::mem_row_major);
        }
}

// ---------------------------------------------------------------------------
// Pass 3 (fused): scores + weighted segment sum + broadcast.
// ---------------------------------------------------------------------------
__global__ void __launch_bounds__(256, 6)
k_score_rep_bcast(const float* __restrict__ emb, float* __restrict__ out) {
    int n = blockIdx.x, tid = threadIdx.x;
    __shared__ __align__(16) float stg[256];
    __shared__ __align__(16) float redw[8][256];
    __shared__ __align__(16) float srep[256];
    int s = g_segstart[n], e = g_segstart[n + 1];
    stg[tid] = g_tg[(size_t)n * 256 + tid];
    __syncthreads();
    int lane = tid & 31, w = tid >> 5;

    float4 tga = *(const float4*)&stg[lane * 8];
    float4 tgb = *(const float4*)&stg[lane * 8 + 4];
    float4 accA = make_float4(0.f, 0.f, 0.f, 0.f);
    float4 accB = make_float4(0.f, 0.f, 0.f, 0.f);

    const float4* base = (const float4*)emb + lane * 2;

    int t = s + 2 * w;
    for (; t + 1 < e; t += 16) {
        float4 a0 = __ldcs(base + (size_t)(t + 0) * 64);
        float4 b0 = __ldcs(base + (size_t)(t + 0) * 64 + 1);
        float4 a1 = __ldcs(base + (size_t)(t + 1) * 64);
        float4 b1 = __ldcs(base + (size_t)(t + 1) * 64 + 1);
        float d0 = a0.x*tga.x + a0.y*tga.y + a0.z*tga.z + a0.w*tga.w
                 + b0.x*tgb.x + b0.y*tgb.y + b0.z*tgb.z + b0.w*tgb.w;
        float d1 = a1.x*tga.x + a1.y*tga.y + a1.z*tga.z + a1.w*tga.w
                 + b1.x*tgb.x + b1.y*tgb.y + b1.z*tgb.z + b1.w*tgb.w;
#pragma unroll
        for (int off = 16; off; off >>= 1) {
            d0 += __shfl_xor_sync(0xffffffffu, d0, off);
            d1 += __shfl_xor_sync(0xffffffffu, d1, off);
        }
        float s0 = 1.f / (1.f + __expf(-d0));
        float s1 = 1.f / (1.f + __expf(-d1));
        accA.x += a0.x*s0 + a1.x*s1;
        accA.y += a0.y*s0 + a1.y*s1;
        accA.z += a0.z*s0 + a1.z*s1;
        accA.w += a0.w*s0 + a1.w*s1;
        accB.x += b0.x*s0 + b1.x*s1;
        accB.y += b0.y*s0 + b1.y*s1;
        accB.z += b0.z*s0 + b1.z*s1;
        accB.w += b0.w*s0 + b1.w*s1;
    }
    if (t < e) {
        float4 a0 = __ldcs(base + (size_t)t * 64);
        float4 b0 = __ldcs(base + (size_t)t * 64 + 1);
        float d0 = a0.x*tga.x + a0.y*tga.y + a0.z*tga.z + a0.w*tga.w
                 + b0.x*tgb.x + b0.y*tgb.y + b0.z*tgb.z + b0.w*tgb.w;
#pragma unroll
        for (int off = 16; off; off >>= 1)
            d0 += __shfl_xor_sync(0xffffffffu, d0, off);
        float s0 = 1.f / (1.f + __expf(-d0));
        accA.x += a0.x*s0; accA.y += a0.y*s0;
        accA.z += a0.z*s0; accA.w += a0.w*s0;
        accB.x += b0.x*s0; accB.y += b0.y*s0;
        accB.z += b0.z*s0; accB.w += b0.w*s0;
    }
    *(float4*)&redw[w][lane * 8]     = accA;
    *(float4*)&redw[w][lane * 8 + 4] = accB;
    __syncthreads();
    float sum = 0.f;
#pragma unroll
    for (int j = 0; j < 8; ++j) sum += redw[j][tid];
    srep[tid] = sum;
    __syncthreads();

    int c = tid & 63;
    int r = tid >> 6;
    float4 rv = *(const float4*)&srep[c * 4];
    float4* ob = (float4*)out + c;
    for (int tt = s + r; tt < e; tt += 4)
        __stcs(ob + (size_t)tt * 64, rv);
}

extern "C" void kernel_launch(void* const* d_in, const int* in_sizes, int n_in,
                              void* d_out, int out_size) {
    const float* emb = (const float*)d_in[0];
    const float* W   = (const float*)d_in[1];
    const int*   obj = (const int*)d_in[2];
    float*       out = (float*)d_out;

    k_bounds<<<(T_TOK + 255) / 256, 256>>>(obj);
    k_segmean<<<N_SEG, 512>>>(emb);
    k_gemm_tanh<<<dim3(N_SEG / 128, D_DIM / 64), 256>>>(W);
    k_score_rep_bcast<<<N_SEG, 256>>>(emb, out);
}